// round 7
// baseline (speedup 1.0000x reference)
#include <cuda_runtime.h>
#include <cstdint>

// DenseGridNet: trilevel bilinear grid features + MLP 13->64->64->3.
// Persistent-CTA GEMM tiling: 128 points/tile, 256 threads (8 warps),
// per-thread tile 4 outs x 8 points, point-pairs packed via fma.rn.f32x2
// (exact fp32). Swizzled activation layout (RS=160 + per-row 16B offset).

#define HID 64
#define EMB 13
#define TILE 128
#define THREADS 256
#define RS 160          // activation row stride in floats (multiple of 32)
#define BLOCKS 444      // 148 SMs x 3 CTAs

typedef unsigned long long u64;

__device__ __forceinline__ u64 pack2(float a) {
    u64 r;
    asm("mov.b64 %0, {%1, %1};" : "=l"(r) : "f"(a));
    return r;
}
__device__ __forceinline__ u64 fma2(u64 a, u64 b, u64 c) {
    u64 d;
    asm("fma.rn.f32x2 %0, %1, %2, %3;" : "=l"(d) : "l"(a), "l"(b), "l"(c));
    return d;
}
__device__ __forceinline__ void unpack2(u64 p, float& lo, float& hi) {
    asm("mov.b64 {%0, %1}, %2;" : "=f"(lo), "=f"(hi) : "l"(p));
}
// Row r starts at r*RS + ((r>>2)&7)*4 floats. RS%32==0 -> bank phase of a row
// depends only on the swizzle term; epilogue float4 stores across rows 4*to+o
// form a bank permutation over to&7.
__device__ __forceinline__ int rowoff(int r) {
    return r * RS + (((r >> 2) & 7) << 2);
}

struct __align__(16) Smem {
    float w1[EMB * HID];
    float b1[HID];
    float w2[HID * HID];
    float b2[HID];
    float w3[HID * 4];    // 64x3 padded to 64x4 (col 3 = 0)
    float b3[4];
    float xs[3 * TILE];
    float A0[EMB * RS];
    float A1[HID * RS];
};

__device__ __forceinline__ float4 bilerp_level(const float4* __restrict__ tab,
                                               int res, float u, float v) {
    float sx = u * (float)res;
    float sy = v * (float)res;
    int x0 = (int)sx;            // truncation; matches astype(int32) for non-neg
    int y0 = (int)sy;
    float wx = sx - (float)x0;
    float wy = sy - (float)y0;
    int x1 = min(x0 + 1, res);
    int y1 = min(y0 + 1, res);
    // Reference indexes with row stride == res (not res+1). Replicate exactly.
    int r0 = y0 * res;
    int r1 = y1 * res;
    float4 v00 = tab[r0 + x0];
    float4 v10 = tab[r0 + x1];
    float4 v01 = tab[r1 + x0];
    float4 v11 = tab[r1 + x1];
    float omwx = 1.0f - wx;
    float omwy = 1.0f - wy;
    float4 o;
    float t, c;
    t = v00.x * omwx + v10.x * wx; c = v01.x * omwx + v11.x * wx; o.x = t * omwy + c * wy;
    t = v00.y * omwx + v10.y * wx; c = v01.y * omwx + v11.y * wx; o.y = t * omwy + c * wy;
    t = v00.z * omwx + v10.z * wx; c = v01.z * omwx + v11.z * wx; o.z = t * omwy + c * wy;
    t = v00.w * omwx + v10.w * wx; c = v01.w * omwx + v11.w * wx; o.w = t * omwy + c * wy;
    return o;
}

__global__ __launch_bounds__(THREADS, 3)
void densegrid_kernel(const float* __restrict__ x,
                      const float4* __restrict__ emb0,
                      const float4* __restrict__ emb1,
                      const float4* __restrict__ emb2,
                      const float* __restrict__ w1, const float* __restrict__ b1,
                      const float* __restrict__ w2, const float* __restrict__ b2,
                      const float* __restrict__ w3, const float* __restrict__ b3,
                      float* __restrict__ out, int n) {
    extern __shared__ char smem_raw[];
    Smem& s = *reinterpret_cast<Smem*>(smem_raw);

    const int tid = threadIdx.x;

    // ---- one-time weight staging (persistent CTA) ----
    for (int t = tid; t < EMB * HID; t += THREADS) s.w1[t] = w1[t];
    for (int t = tid; t < HID; t += THREADS) s.b1[t] = b1[t];
    for (int t = tid; t < HID * HID; t += THREADS) s.w2[t] = w2[t];
    for (int t = tid; t < HID; t += THREADS) s.b2[t] = b2[t];
    for (int t = tid; t < HID * 4; t += THREADS) {
        int r = t >> 2, c = t & 3;
        s.w3[t] = (c < 3) ? w3[r * 3 + c] : 0.0f;
    }
    if (tid < 4) s.b3[tid] = (tid < 3) ? b3[tid] : 0.0f;

    const int to = tid & 15;   // output quad: outs [4*to .. 4*to+3]
    const int tp = tid >> 4;   // point group: pts [8*tp .. 8*tp+7]
    const int ntiles = (n + TILE - 1) / TILE;

    for (int tile = blockIdx.x; tile < ntiles; tile += gridDim.x) {
        const int base = tile * TILE;

        // ---- stage x coalesced (384 floats) ----
        for (int t = tid; t < 3 * TILE; t += THREADS) {
            int gi = base * 3 + t;
            s.xs[t] = (gi < n * 3) ? x[gi] : 0.0f;
        }
        __syncthreads();

        // ---- phase 0: gather. Threads 0-127: idf+level0 for pt=tid.
        //      Threads 128-255: levels 1+2 for pt=tid-128. ----
        {
            int p = tid & (TILE - 1);
            float u = s.xs[3 * p + 1];
            float v = s.xs[3 * p + 2];
            if (tid < TILE) {
                float idf = s.xs[3 * p + 0];
                float4 f0 = bilerp_level(emb0, 512, u, v);
                s.A0[rowoff(0) + p] = idf;
                s.A0[rowoff(1) + p] = f0.x; s.A0[rowoff(2) + p] = f0.y;
                s.A0[rowoff(3) + p] = f0.z; s.A0[rowoff(4) + p] = f0.w;
            } else {
                float4 f1 = bilerp_level(emb1, 264, u, v);
                float4 f2 = bilerp_level(emb2, 16,  u, v);
                s.A0[rowoff(5)  + p] = f1.x; s.A0[rowoff(6)  + p] = f1.y;
                s.A0[rowoff(7)  + p] = f1.z; s.A0[rowoff(8)  + p] = f1.w;
                s.A0[rowoff(9)  + p] = f2.x; s.A0[rowoff(10) + p] = f2.y;
                s.A0[rowoff(11) + p] = f2.z; s.A0[rowoff(12) + p] = f2.w;
            }
        }
        __syncthreads();

        // ---- phase 1: 13 -> 64 + relu ----
        {
            u64 acc[4][4];
            #pragma unroll
            for (int o = 0; o < 4; o++) {
                u64 bb = pack2(s.b1[4 * to + o]);
                #pragma unroll
                for (int pp = 0; pp < 4; pp++) acc[o][pp] = bb;
            }
            #pragma unroll
            for (int i = 0; i < EMB; i++) {
                float4 w = *(const float4*)&s.w1[i * HID + 4 * to];
                u64 wp0 = pack2(w.x), wp1 = pack2(w.y), wp2 = pack2(w.z), wp3 = pack2(w.w);
                const ulonglong2* av = (const ulonglong2*)&s.A0[rowoff(i) + 8 * tp];
                ulonglong2 q0 = av[0], q1 = av[1];
                u64 a[4] = {q0.x, q0.y, q1.x, q1.y};
                #pragma unroll
                for (int pp = 0; pp < 4; pp++) {
                    acc[0][pp] = fma2(wp0, a[pp], acc[0][pp]);
                    acc[1][pp] = fma2(wp1, a[pp], acc[1][pp]);
                    acc[2][pp] = fma2(wp2, a[pp], acc[2][pp]);
                    acc[3][pp] = fma2(wp3, a[pp], acc[3][pp]);
                }
            }
            #pragma unroll
            for (int o = 0; o < 4; o++) {
                float4* row = (float4*)&s.A1[rowoff(4 * to + o) + 8 * tp];
                #pragma unroll
                for (int k = 0; k < 2; k++) {
                    float l0, h0, l1, h1;
                    unpack2(acc[o][2 * k + 0], l0, h0);
                    unpack2(acc[o][2 * k + 1], l1, h1);
                    row[k] = make_float4(fmaxf(l0, 0.0f), fmaxf(h0, 0.0f),
                                         fmaxf(l1, 0.0f), fmaxf(h1, 0.0f));
                }
            }
        }
        __syncthreads();

        // ---- phase 2: 64 -> 64 + relu, in-place on A1 ----
        {
            u64 acc[4][4];
            #pragma unroll
            for (int o = 0; o < 4; o++) {
                u64 bb = pack2(s.b2[4 * to + o]);
                #pragma unroll
                for (int pp = 0; pp < 4; pp++) acc[o][pp] = bb;
            }
            #pragma unroll 16
            for (int i = 0; i < HID; i++) {
                float4 w = *(const float4*)&s.w2[i * HID + 4 * to];
                u64 wp0 = pack2(w.x), wp1 = pack2(w.y), wp2 = pack2(w.z), wp3 = pack2(w.w);
                const ulonglong2* av = (const ulonglong2*)&s.A1[rowoff(i) + 8 * tp];
                ulonglong2 q0 = av[0], q1 = av[1];
                u64 a[4] = {q0.x, q0.y, q1.x, q1.y};
                #pragma unroll
                for (int pp = 0; pp < 4; pp++) {
                    acc[0][pp] = fma2(wp0, a[pp], acc[0][pp]);
                    acc[1][pp] = fma2(wp1, a[pp], acc[1][pp]);
                    acc[2][pp] = fma2(wp2, a[pp], acc[2][pp]);
                    acc[3][pp] = fma2(wp3, a[pp], acc[3][pp]);
                }
            }
            __syncthreads();   // all reads of A1 complete before overwrite
            #pragma unroll
            for (int o = 0; o < 4; o++) {
                float4* row = (float4*)&s.A1[rowoff(4 * to + o) + 8 * tp];
                #pragma unroll
                for (int k = 0; k < 2; k++) {
                    float l0, h0, l1, h1;
                    unpack2(acc[o][2 * k + 0], l0, h0);
                    unpack2(acc[o][2 * k + 1], l1, h1);
                    row[k] = make_float4(fmaxf(l0, 0.0f), fmaxf(h0, 0.0f),
                                         fmaxf(l1, 0.0f), fmaxf(h1, 0.0f));
                }
            }
        }
        __syncthreads();

        // ---- phase 3: 64 -> 3, one point per thread (threads 0-127) ----
        if (tid < TILE) {
            u64 p01 = *(const u64*)&s.b3[0];
            u64 p23 = *(const u64*)&s.b3[2];
            const ulonglong2* w3v = (const ulonglong2*)s.w3;
            #pragma unroll 8
            for (int i = 0; i < HID; i++) {
                u64 ap = pack2(s.A1[rowoff(i) + tid]);
                ulonglong2 wq = w3v[i];
                p01 = fma2(ap, wq.x, p01);
                p23 = fma2(ap, wq.y, p23);
            }
            float o0, o1, o2, o3;
            unpack2(p01, o0, o1);
            unpack2(p23, o2, o3);
            int idx = base + tid;
            if (idx < n) {
                out[idx * 3 + 0] = o0;
                out[idx * 3 + 1] = o1;
                out[idx * 3 + 2] = o2;
            }
        }
        __syncthreads();   // protect xs/A1 from next tile's writes
    }
}

extern "C" void kernel_launch(void* const* d_in, const int* in_sizes, int n_in,
                              void* d_out, int out_size) {
    const float* x    = (const float*)d_in[0];
    const float4* e0  = (const float4*)d_in[1];
    const float4* e1  = (const float4*)d_in[2];
    const float4* e2  = (const float4*)d_in[3];
    const float* w1   = (const float*)d_in[4];
    const float* b1   = (const float*)d_in[5];
    const float* w2   = (const float*)d_in[6];
    const float* b2   = (const float*)d_in[7];
    const float* w3   = (const float*)d_in[8];
    const float* b3   = (const float*)d_in[9];
    float* out        = (float*)d_out;
    int n = in_sizes[0] / 3;
    (void)n_in; (void)out_size;
    cudaFuncSetAttribute(densegrid_kernel,
                         cudaFuncAttributeMaxDynamicSharedMemorySize,
                         (int)sizeof(Smem));
    densegrid_kernel<<<BLOCKS, THREADS, sizeof(Smem)>>>(
        x, e0, e1, e2, w1, b1, w2, b2, w3, b3, out, n);
}

// round 9
// speedup vs baseline: 2.1208x; 2.1208x over previous
#include <cuda_runtime.h>
#include <cuda_bf16.h>
#include <cstdint>

// DenseGridNet via warp-level mma.sync bf16 (m16n8k16) with split-bf16 x3
// compensation (fp32-grade accuracy). Each warp owns 16 points and computes
// all 64 hidden units; C fragments feed the next layer's A fragments directly
// in registers (m16n8 C layout == m16k16 A layout halves). Weights are
// pre-converted once per persistent CTA into lane-indexed smem fragments.

#define THREADS 256
#define TILE 128
#define NCTA 296
#define FS 132   // ftile row stride in floats

__device__ __forceinline__ void splitpack(float v0, float v1,
                                          uint32_t& hi, uint32_t& lo) {
    __nv_bfloat16 h0 = __float2bfloat16(v0);
    __nv_bfloat16 h1 = __float2bfloat16(v1);
    float l0 = v0 - __bfloat162float(h0);
    float l1 = v1 - __bfloat162float(h1);
    __nv_bfloat162 hp = __halves2bfloat162(h0, h1);   // .x in low 16 bits
    __nv_bfloat162 lp = __halves2bfloat162(__float2bfloat16(l0),
                                           __float2bfloat16(l1));
    __builtin_memcpy(&hi, &hp, 4);
    __builtin_memcpy(&lo, &lp, 4);
}

__device__ __forceinline__ void mma16816(float c[4], const uint32_t a[4],
                                         uint32_t b0, uint32_t b1) {
    asm volatile(
        "mma.sync.aligned.m16n8k16.row.col.f32.bf16.bf16.f32 "
        "{%0,%1,%2,%3}, {%4,%5,%6,%7}, {%8,%9}, {%0,%1,%2,%3};"
        : "+f"(c[0]), "+f"(c[1]), "+f"(c[2]), "+f"(c[3])
        : "r"(a[0]), "r"(a[1]), "r"(a[2]), "r"(a[3]), "r"(b0), "r"(b1));
}

__device__ __forceinline__ float4 bilerp_level(const float4* __restrict__ tab,
                                               int res, float u, float v) {
    float sx = u * (float)res, sy = v * (float)res;
    int x0 = (int)sx, y0 = (int)sy;           // truncation == astype(int32)
    float wx = sx - (float)x0, wy = sy - (float)y0;
    int x1 = min(x0 + 1, res), y1 = min(y0 + 1, res);
    int r0 = y0 * res, r1 = y1 * res;         // reference row stride == res
    float4 v00 = tab[r0 + x0], v10 = tab[r0 + x1];
    float4 v01 = tab[r1 + x0], v11 = tab[r1 + x1];
    float omwx = 1.0f - wx, omwy = 1.0f - wy;
    float4 o; float t, c;
    t = v00.x*omwx + v10.x*wx; c = v01.x*omwx + v11.x*wx; o.x = t*omwy + c*wy;
    t = v00.y*omwx + v10.y*wx; c = v01.y*omwx + v11.y*wx; o.y = t*omwy + c*wy;
    t = v00.z*omwx + v10.z*wx; c = v01.z*omwx + v11.z*wx; o.z = t*omwy + c*wy;
    t = v00.w*omwx + v10.w*wx; c = v01.w*omwx + v11.w*wx; o.w = t*omwy + c*wy;
    return o;
}

__global__ __launch_bounds__(THREADS, 2)
void densegrid_kernel(const float* __restrict__ x,
                      const float4* __restrict__ emb0,
                      const float4* __restrict__ emb1,
                      const float4* __restrict__ emb2,
                      const float* __restrict__ w1, const float* __restrict__ b1,
                      const float* __restrict__ w2, const float* __restrict__ b2,
                      const float* __restrict__ w3, const float* __restrict__ b3,
                      float* __restrict__ out, int n) {
    // B fragments: [g-tile *(kk)][lane] -> uint2{b0,b1}. Conflict-free LDS.64.
    __shared__ uint2 B1h[8 * 32],  B1l[8 * 32];    // layer1: 8 n-tiles, 1 kstep
    __shared__ uint2 B2h[32 * 32], B2l[32 * 32];   // layer2: 8 n-tiles x 4 ksteps
    __shared__ uint2 B3h[4 * 32],  B3l[4 * 32];    // layer3: 1 n-tile x 4 ksteps
    __shared__ float b1s[64], b2s[64], b3s[8];
    __shared__ float xs[3 * TILE];
    __shared__ float ftile[16 * FS];               // [k][point], rows 13-15 = 0

    const int tid  = threadIdx.x;
    const int wid  = tid >> 5;
    const int lane = tid & 31;
    const int grp  = lane >> 2;
    const int t4   = lane & 3;

    // ---- one-time weight fragment staging ----
    for (int i = tid; i < 32 * 32; i += THREADS) {      // layer 2
        int ln = i & 31, gkk = i >> 5;
        int kk = gkk & 3, g = gkk >> 2;
        int tt = ln & 3, gp = ln >> 2;
        int nn = 8 * g + gp;
        int k0 = 16 * kk + 2 * tt;
        uint32_t h0, l0, h1, l1;
        splitpack(w2[(k0 + 0) * 64 + nn], w2[(k0 + 1) * 64 + nn], h0, l0);
        splitpack(w2[(k0 + 8) * 64 + nn], w2[(k0 + 9) * 64 + nn], h1, l1);
        B2h[i] = make_uint2(h0, h1);
        B2l[i] = make_uint2(l0, l1);
    }
    for (int i = tid; i < 8 * 32; i += THREADS) {       // layer 1 (K pad 13->16)
        int ln = i & 31, g = i >> 5;
        int tt = ln & 3, gp = ln >> 2;
        int nn = 8 * g + gp;
        int k0 = 2 * tt;
        float wa = w1[(k0 + 0) * 64 + nn];
        float wb = w1[(k0 + 1) * 64 + nn];
        float wc = (k0 + 8 < 13) ? w1[(k0 + 8) * 64 + nn] : 0.0f;
        float wd = (k0 + 9 < 13) ? w1[(k0 + 9) * 64 + nn] : 0.0f;
        uint32_t h0, l0, h1, l1;
        splitpack(wa, wb, h0, l0);
        splitpack(wc, wd, h1, l1);
        B1h[i] = make_uint2(h0, h1);
        B1l[i] = make_uint2(l0, l1);
    }
    for (int i = tid; i < 4 * 32; i += THREADS) {       // layer 3 (N pad 3->8)
        int ln = i & 31, kk = i >> 5;
        int tt = ln & 3, gp = ln >> 2;
        int k0 = 16 * kk + 2 * tt;
        float wa = (gp < 3) ? w3[(k0 + 0) * 3 + gp] : 0.0f;
        float wb = (gp < 3) ? w3[(k0 + 1) * 3 + gp] : 0.0f;
        float wc = (gp < 3) ? w3[(k0 + 8) * 3 + gp] : 0.0f;
        float wd = (gp < 3) ? w3[(k0 + 9) * 3 + gp] : 0.0f;
        uint32_t h0, l0, h1, l1;
        splitpack(wa, wb, h0, l0);
        splitpack(wc, wd, h1, l1);
        B3h[i] = make_uint2(h0, h1);
        B3l[i] = make_uint2(l0, l1);
    }
    for (int i = tid; i < 64; i += THREADS) { b1s[i] = b1[i]; b2s[i] = b2[i]; }
    if (tid < 8) b3s[tid] = (tid < 3) ? b3[tid] : 0.0f;
    for (int i = tid; i < 16 * FS; i += THREADS) ftile[i] = 0.0f;
    __syncthreads();

    const int n3 = n * 3;
    const int ntiles = (n + TILE - 1) / TILE;

    for (int tile = blockIdx.x; tile < ntiles; tile += gridDim.x) {
        const int base = tile * TILE;

        // ---- stage x coalesced ----
        for (int i = tid; i < 3 * TILE; i += THREADS) {
            int gi = base * 3 + i;
            xs[i] = (gi < n3) ? x[gi] : 0.0f;
        }
        __syncthreads();

        // ---- gather: threads 0-127 idf+level0 of pt p; 128-255 levels 1+2 ----
        {
            int p = tid & 127;
            float u = xs[3 * p + 1], v = xs[3 * p + 2];
            if (tid < 128) {
                ftile[0 * FS + p] = xs[3 * p];
                float4 f0 = bilerp_level(emb0, 512, u, v);
                ftile[1 * FS + p] = f0.x; ftile[2 * FS + p] = f0.y;
                ftile[3 * FS + p] = f0.z; ftile[4 * FS + p] = f0.w;
            } else {
                float4 f1 = bilerp_level(emb1, 264, u, v);
                float4 f2 = bilerp_level(emb2, 16,  u, v);
                ftile[5 * FS + p]  = f1.x; ftile[6 * FS + p]  = f1.y;
                ftile[7 * FS + p]  = f1.z; ftile[8 * FS + p]  = f1.w;
                ftile[9 * FS + p]  = f2.x; ftile[10 * FS + p] = f2.y;
                ftile[11 * FS + p] = f2.z; ftile[12 * FS + p] = f2.w;
            }
        }
        __syncthreads();

        // ---- A0 fragments (warp's 16 points, K=16) ----
        uint32_t a0h[4], a0l[4];
        {
            int p0 = 16 * wid + grp;
            int k0 = 2 * t4;
            splitpack(ftile[(k0 + 0) * FS + p0],     ftile[(k0 + 1) * FS + p0],     a0h[0], a0l[0]);
            splitpack(ftile[(k0 + 0) * FS + p0 + 8], ftile[(k0 + 1) * FS + p0 + 8], a0h[1], a0l[1]);
            splitpack(ftile[(k0 + 8) * FS + p0],     ftile[(k0 + 9) * FS + p0],     a0h[2], a0l[2]);
            splitpack(ftile[(k0 + 8) * FS + p0 + 8], ftile[(k0 + 9) * FS + p0 + 8], a0h[3], a0l[3]);
        }

        // ---- layer 1: 16 -> 64, bias+relu, split -> A1 fragments ----
        uint32_t a1h[4][4], a1l[4][4];
        #pragma unroll
        for (int g = 0; g < 8; g++) {
            float c[4];
            float2 bb = *(const float2*)&b1s[8 * g + 2 * t4];
            c[0] = bb.x; c[1] = bb.y; c[2] = bb.x; c[3] = bb.y;
            uint2 bh = B1h[g * 32 + lane];
            uint2 bl = B1l[g * 32 + lane];
            mma16816(c, a0h, bh.x, bh.y);
            mma16816(c, a0h, bl.x, bl.y);
            mma16816(c, a0l, bh.x, bh.y);
            int kk = g >> 1, hf = g & 1;
            splitpack(fmaxf(c[0], 0.0f), fmaxf(c[1], 0.0f),
                      a1h[kk][2 * hf + 0], a1l[kk][2 * hf + 0]);
            splitpack(fmaxf(c[2], 0.0f), fmaxf(c[3], 0.0f),
                      a1h[kk][2 * hf + 1], a1l[kk][2 * hf + 1]);
        }

        // ---- layer 2: 64 -> 64, bias+relu, split -> A2 fragments ----
        uint32_t a2h[4][4], a2l[4][4];
        #pragma unroll
        for (int g = 0; g < 8; g++) {
            float c[4];
            float2 bb = *(const float2*)&b2s[8 * g + 2 * t4];
            c[0] = bb.x; c[1] = bb.y; c[2] = bb.x; c[3] = bb.y;
            #pragma unroll
            for (int kk = 0; kk < 4; kk++) {
                uint2 bh = B2h[(g * 4 + kk) * 32 + lane];
                uint2 bl = B2l[(g * 4 + kk) * 32 + lane];
                mma16816(c, a1h[kk], bh.x, bh.y);
                mma16816(c, a1h[kk], bl.x, bl.y);
                mma16816(c, a1l[kk], bh.x, bh.y);
            }
            int kk2 = g >> 1, hf = g & 1;
            splitpack(fmaxf(c[0], 0.0f), fmaxf(c[1], 0.0f),
                      a2h[kk2][2 * hf + 0], a2l[kk2][2 * hf + 0]);
            splitpack(fmaxf(c[2], 0.0f), fmaxf(c[3], 0.0f),
                      a2h[kk2][2 * hf + 1], a2l[kk2][2 * hf + 1]);
        }

        // ---- layer 3: 64 -> 8 (3 used), write output ----
        {
            float c[4];
            float2 bb = *(const float2*)&b3s[2 * t4];
            c[0] = bb.x; c[1] = bb.y; c[2] = bb.x; c[3] = bb.y;
            #pragma unroll
            for (int kk = 0; kk < 4; kk++) {
                uint2 bh = B3h[kk * 32 + lane];
                uint2 bl = B3l[kk * 32 + lane];
                mma16816(c, a2h[kk], bh.x, bh.y);
                mma16816(c, a2h[kk], bl.x, bl.y);
                mma16816(c, a2l[kk], bh.x, bh.y);
            }
            int p0 = base + 16 * wid + grp;
            int col = 2 * t4;
            if (col < 3) {
                if (p0 < n)     out[p0 * 3 + col]       = c[0];
                if (p0 + 8 < n) out[(p0 + 8) * 3 + col] = c[2];
            }
            if (col + 1 < 3) {
                if (p0 < n)     out[p0 * 3 + col + 1]       = c[1];
                if (p0 + 8 < n) out[(p0 + 8) * 3 + col + 1] = c[3];
            }
        }
        // gather(i+1) writes ftile only after the sync following xs staging,
        // which all warps reach only after finishing compute(i): no extra sync.
    }
}

extern "C" void kernel_launch(void* const* d_in, const int* in_sizes, int n_in,
                              void* d_out, int out_size) {
    const float* x    = (const float*)d_in[0];
    const float4* e0  = (const float4*)d_in[1];
    const float4* e1  = (const float4*)d_in[2];
    const float4* e2  = (const float4*)d_in[3];
    const float* w1   = (const float*)d_in[4];
    const float* b1   = (const float*)d_in[5];
    const float* w2   = (const float*)d_in[6];
    const float* b2   = (const float*)d_in[7];
    const float* w3   = (const float*)d_in[8];
    const float* b3   = (const float*)d_in[9];
    float* out        = (float*)d_out;
    int n = in_sizes[0] / 3;
    (void)n_in; (void)out_size;
    densegrid_kernel<<<NCTA, THREADS>>>(
        x, e0, e1, e2, w1, b1, w2, b2, w3, b3, out, n);
}